// round 14
// baseline (speedup 1.0000x reference)
#include <cuda_runtime.h>
#include <cuda_bf16.h>
#include <cstdint>

// ---------------------------------------------------------------------------
// FreeConvNetwork, B=8192. LL2 + LL3 on mma.sync bf16 hi/lo-split tensor
// cores (fp32 accumulate). Proven-clean patterns only:
//   - pack/split ONLY in fills (registers) and standalone prep kernels
//   - hmma epilogues write fp32 ONLY (packed epilogues -> 384MiB lmem pool)
//   - conflict-free fragment-plane smem (Ahi/Alo[k2][m], Bhi/Blo[k2][n],
//     XOR swizzle col ^= (k2&3)*8); inner loop pure LDS.32 + HMMA.
// NEW in this round: register-staged double buffering. Chunk k+1's gmem
// loads are issued right after the fill-sync and complete during chunk k's
// 48 MMAs; named-scalar prefetch state only (no cp.async, no arrays).
// value = hi + lo (bf16 each); D = Ahi*Bhi + Ahi*Blo + Alo*Bhi.
// ---------------------------------------------------------------------------

#define BATCH 8192

__device__ float    g_xT [784        * BATCH];   // (28*28, B)
__device__ float    g_h1 [32  * 169  * BATCH];   // fp32
__device__ float    g_h2 [64  * 36   * BATCH];   // fp32
__device__ float    g_h3 [2048       * BATCH];   // fp32
__device__ unsigned g_W2p[36 * 64  * 288];       // (loc, o, k) packed pairs
__device__ unsigned g_W3p[16 * 128 * 576];       // (loc, o, k) packed pairs

__device__ __forceinline__ unsigned pack_pair(float v) {
    __nv_bfloat16 h = __float2bfloat16(v);
    float r = v - __bfloat162float(h);
    __nv_bfloat16 l = __float2bfloat16(r);
    return ((unsigned)__bfloat16_as_ushort(l) << 16) | (unsigned)__bfloat16_as_ushort(h);
}

// Split two fp32 (consecutive k) into hi-fragment and lo-fragment u32s.
__device__ __forceinline__ void pack2(float a, float b, unsigned& hi, unsigned& lo) {
    __nv_bfloat16 ha = __float2bfloat16(a);
    __nv_bfloat16 hb = __float2bfloat16(b);
    float ra = a - __bfloat162float(ha);
    float rb = b - __bfloat162float(hb);
    __nv_bfloat16 la = __float2bfloat16(ra);
    __nv_bfloat16 lb = __float2bfloat16(rb);
    hi = ((unsigned)__bfloat16_as_ushort(hb) << 16) | (unsigned)__bfloat16_as_ushort(ha);
    lo = ((unsigned)__bfloat16_as_ushort(lb) << 16) | (unsigned)__bfloat16_as_ushort(la);
}

#define MMA(c, a0, a1, a2, a3, b) \
    asm volatile( \
        "mma.sync.aligned.m16n8k16.row.col.f32.bf16.bf16.f32 " \
        "{%0,%1,%2,%3}, {%4,%5,%6,%7}, {%8,%9}, {%0,%1,%2,%3};" \
        : "+f"(c.x), "+f"(c.y), "+f"(c.z), "+f"(c.w) \
        : "r"(a0), "r"(a1), "r"(a2), "r"(a3), "r"(b.x), "r"(b.y))

#define PERM_HI(x, y) __byte_perm(x, y, 0x5410)
#define PERM_LO(x, y) __byte_perm(x, y, 0x7632)

// ---------------------------------------------------------------------------
// x (B,784) -> xT (784,B)   [proven]
// ---------------------------------------------------------------------------
__global__ void transpose_x_k(const float* __restrict__ x) {
    __shared__ float tile[32][33];
    int c  = blockIdx.x * 32 + threadIdx.x;
    int r0 = blockIdx.y * 32;
    #pragma unroll
    for (int i = threadIdx.y; i < 32; i += 8) {
        int r = r0 + i;
        tile[i][threadIdx.x] = (c < 784) ? x[r * 784 + c] : 0.f;
    }
    __syncthreads();
    int oc  = r0 + threadIdx.x;
    int or0 = blockIdx.x * 32;
    #pragma unroll
    for (int i = threadIdx.y; i < 32; i += 8) {
        int orow = or0 + i;
        if (orow < 784) g_xT[orow * BATCH + oc] = tile[threadIdx.x][i];
    }
}

// ---------------------------------------------------------------------------
// Weight prep   [proven]
// ---------------------------------------------------------------------------
__global__ void wpack2_k(const float* __restrict__ W) {
    int idx = blockIdx.x * 256 + threadIdx.x;
    if (idx >= 36 * 64 * 288) return;
    int k   = idx % 288;
    int o   = (idx / 288) % 64;
    int loc = idx / (288 * 64);
    g_W2p[idx] = pack_pair(W[(o * 288 + k) * 36 + loc]);
}
__global__ void wpack3_k(const float* __restrict__ W) {
    int idx = blockIdx.x * 256 + threadIdx.x;
    if (idx >= 16 * 128 * 576) return;
    int k   = idx % 576;
    int o   = (idx / 576) % 128;
    int loc = idx / (576 * 128);
    g_W3p[idx] = pack_pair(W[(o * 576 + k) * 16 + loc]);
}

// ---------------------------------------------------------------------------
// LL1 (CUDA core, K=9), fp32 out.   [proven]
// ---------------------------------------------------------------------------
__global__ __launch_bounds__(256) void ll1_k(const float* __restrict__ W1,
                                             const float* __restrict__ b1) {
    int loc = blockIdx.x;
    int i = loc / 13, j = loc % 13;
    int b = blockIdx.y * 256 + threadIdx.x;

    __shared__ float ws[32 * 9];
    __shared__ float bs[32];
    for (int t = threadIdx.x; t < 32 * 9; t += 256) {
        int o = t / 9, k = t % 9;
        ws[t] = W1[(o * 9 + k) * 169 + loc];
    }
    if (threadIdx.x < 32) bs[threadIdx.x] = b1[threadIdx.x * 169 + loc];
    __syncthreads();

    float v[9];
    #pragma unroll
    for (int k = 0; k < 9; k++) {
        int di = k / 3, dj = k % 3;
        v[k] = g_xT[((2 * i + di) * 28 + (2 * j + dj)) * BATCH + b];
    }
    #pragma unroll
    for (int o = 0; o < 32; o++) {
        float acc = bs[o];
        #pragma unroll
        for (int k = 0; k < 9; k++) acc = fmaf(ws[o * 9 + k], v[k], acc);
        g_h1[(o * 169 + loc) * BATCH + b] = fmaxf(acc, 0.f);
    }
}

// ---------------------------------------------------------------------------
// hmma building-block macros (fragment planes + XOR swizzle + reg prefetch).
// ---------------------------------------------------------------------------
// Prefetch chunk at K0 into named registers (va0..vb1, qa, qb).
#define ALDG_(src, K0) do { \
    int _m4 = lane * 4; \
    { int _k = (K0) + wid * 2; \
      va0 = *(const float4*)(src + rowoffS[_k]     + m0 + _m4); \
      va1 = *(const float4*)(src + rowoffS[_k + 1] + m0 + _m4); } \
    { int _k = (K0) + (8 + wid) * 2; \
      vb0 = *(const float4*)(src + rowoffS[_k]     + m0 + _m4); \
      vb1 = *(const float4*)(src + rowoffS[_k + 1] + m0 + _m4); } \
} while (0)

#define BLDG_(wloc, KREAL, K0) do { \
    { int _n = tid >> 3; \
      qa = *(const uint4*)(wloc + (size_t)_n * (KREAL) + (K0) + (tid & 7) * 4); } \
    { int _n = 32 + (tid >> 3); \
      qb = *(const uint4*)(wloc + (size_t)_n * (KREAL) + (K0) + (tid & 7) * 4); } \
} while (0)

// Store prefetched registers into the fragment-plane smem (swizzled).
#define ASTORE_() do { \
    int _m4 = lane * 4; \
    { int _k2 = wid; \
      uint4 hv, lv; \
      pack2(va0.x, va1.x, hv.x, lv.x); \
      pack2(va0.y, va1.y, hv.y, lv.y); \
      pack2(va0.z, va1.z, hv.z, lv.z); \
      pack2(va0.w, va1.w, hv.w, lv.w); \
      int _sc = _m4 ^ ((_k2 & 3) * 8); \
      *(uint4*)&Ahi[_k2][_sc] = hv; \
      *(uint4*)&Alo[_k2][_sc] = lv; } \
    { int _k2 = 8 + wid; \
      uint4 hv, lv; \
      pack2(vb0.x, vb1.x, hv.x, lv.x); \
      pack2(vb0.y, vb1.y, hv.y, lv.y); \
      pack2(vb0.z, vb1.z, hv.z, lv.z); \
      pack2(vb0.w, vb1.w, hv.w, lv.w); \
      int _sc = _m4 ^ ((_k2 & 3) * 8); \
      *(uint4*)&Ahi[_k2][_sc] = hv; \
      *(uint4*)&Alo[_k2][_sc] = lv; } \
} while (0)

#define BSTORE_() do { \
    int _k2 = (tid & 7) * 2; \
    int _s0 = (_k2 & 3) * 8, _s1 = ((_k2 + 1) & 3) * 8; \
    { int _n = tid >> 3; \
      Bhi[_k2][_n ^ _s0]     = PERM_HI(qa.x, qa.y); \
      Blo[_k2][_n ^ _s0]     = PERM_LO(qa.x, qa.y); \
      Bhi[_k2 + 1][_n ^ _s1] = PERM_HI(qa.z, qa.w); \
      Blo[_k2 + 1][_n ^ _s1] = PERM_LO(qa.z, qa.w); } \
    { int _n = 32 + (tid >> 3); \
      Bhi[_k2][_n ^ _s0]     = PERM_HI(qb.x, qb.y); \
      Blo[_k2][_n ^ _s0]     = PERM_LO(qb.x, qb.y); \
      Bhi[_k2 + 1][_n ^ _s1] = PERM_HI(qb.z, qb.w); \
      Blo[_k2 + 1][_n ^ _s1] = PERM_LO(qb.z, qb.w); } \
} while (0)

#define LOADB2_(NIv, bh, bl) do { \
    int _n  = wn * 32 + (NIv) * 8 + (lane >> 2); \
    int _k2 = kb2 + (lane & 3); \
    int _s  = (_k2 & 3) * 8; \
    bh.x = Bhi[_k2][_n ^ _s];  bh.y = Bhi[_k2 + 4][_n ^ _s]; \
    bl.x = Blo[_k2][_n ^ _s];  bl.y = Blo[_k2 + 4][_n ^ _s]; \
} while (0)

#define MIBLOCK2_(MI, c0, c1, c2, c3) do { \
    int _m  = wm * 32 + (MI) * 16 + (lane >> 2); \
    int _k2 = kb2 + (lane & 3); \
    int _s  = (_k2 & 3) * 8; \
    unsigned ah0 = Ahi[_k2][_m ^ _s],     ah1 = Ahi[_k2][(_m + 8) ^ _s]; \
    unsigned ah2 = Ahi[_k2 + 4][_m ^ _s], ah3 = Ahi[_k2 + 4][(_m + 8) ^ _s]; \
    unsigned al0 = Alo[_k2][_m ^ _s],     al1 = Alo[_k2][(_m + 8) ^ _s]; \
    unsigned al2 = Alo[_k2 + 4][_m ^ _s], al3 = Alo[_k2 + 4][(_m + 8) ^ _s]; \
    MMA(c0, ah0, ah1, ah2, ah3, bh0); \
    MMA(c0, ah0, ah1, ah2, ah3, bl0); \
    MMA(c0, al0, al1, al2, al3, bh0); \
    MMA(c1, ah0, ah1, ah2, ah3, bh1); \
    MMA(c1, ah0, ah1, ah2, ah3, bl1); \
    MMA(c1, al0, al1, al2, al3, bh1); \
    MMA(c2, ah0, ah1, ah2, ah3, bh2); \
    MMA(c2, ah0, ah1, ah2, ah3, bl2); \
    MMA(c2, al0, al1, al2, al3, bh2); \
    MMA(c3, ah0, ah1, ah2, ah3, bh3); \
    MMA(c3, ah0, ah1, ah2, ah3, bl3); \
    MMA(c3, al0, al1, al2, al3, bh3); \
} while (0)

#define KSTEP_() do { \
    uint2 bh0, bl0, bh1, bl1, bh2, bl2, bh3, bl3; \
    LOADB2_(0, bh0, bl0); LOADB2_(1, bh1, bl1); \
    LOADB2_(2, bh2, bl2); LOADB2_(3, bh3, bl3); \
    MIBLOCK2_(0, c00, c01, c02, c03); \
    MIBLOCK2_(1, c10, c11, c12, c13); \
} while (0)

// fp32 epilogue ONLY.   [proven]
#define EPIF_(dst, LOCS, MI, NIv, c) do { \
    int _m = m0 + wm * 32 + (MI) * 16 + (lane >> 2); \
    int _ol = wn * 32 + (NIv) * 8 + (lane & 3) * 2; \
    int _o  = n0 + _ol; \
    float _b0 = biasS[_ol], _b1 = biasS[_ol + 1]; \
    size_t _ba0 = (size_t)(_o * (LOCS) + loc) * BATCH; \
    size_t _ba1 = (size_t)((_o + 1) * (LOCS) + loc) * BATCH; \
    dst[_ba0 + _m]     = fmaxf(c.x + _b0, 0.f); \
    dst[_ba1 + _m]     = fmaxf(c.y + _b1, 0.f); \
    dst[_ba0 + _m + 8] = fmaxf(c.z + _b0, 0.f); \
    dst[_ba1 + _m + 8] = fmaxf(c.w + _b1, 0.f); \
} while (0)

// ---------------------------------------------------------------------------
// LL2 on mma.sync. N=64, K=288, 36 locs. CTA=(loc, 128-batch); 8 warps 4m x 2n.
// ---------------------------------------------------------------------------
__global__ __launch_bounds__(256, 1) void ll2_hmma_k(const float* __restrict__ b2) {
    __shared__ unsigned Ahi[16][128], Alo[16][128];
    __shared__ unsigned Bhi[16][64],  Blo[16][64];
    __shared__ int   rowoffS[288];
    __shared__ float biasS[64];

    int tid  = threadIdx.x;
    int lane = tid & 31;
    int wid  = tid >> 5;
    int wn   = wid & 1;
    int wm   = wid >> 1;
    int loc  = blockIdx.x;
    int m0   = blockIdx.y * 128;
    const int n0 = 0;
    int li = loc / 6, lj = loc % 6;

    for (int k = tid; k < 288; k += 256) {
        int c = k / 9, r = (k % 9) / 3, cc = k % 3;
        rowoffS[k] = (c * 169 + (2 * li + r) * 13 + (2 * lj + cc)) * BATCH;
    }
    if (tid < 64) biasS[tid] = b2[tid * 36 + loc];
    __syncthreads();

    float4 c00 = {0,0,0,0}, c01 = {0,0,0,0}, c02 = {0,0,0,0}, c03 = {0,0,0,0};
    float4 c10 = {0,0,0,0}, c11 = {0,0,0,0}, c12 = {0,0,0,0}, c13 = {0,0,0,0};

    const unsigned* wloc = g_W2p + (size_t)loc * 64 * 288;

    float4 va0, va1, vb0, vb1;
    uint4 qa, qb;
    ALDG_(g_h1, 0);
    BLDG_(wloc, 288, 0);

    for (int k0 = 0; k0 < 288; k0 += 32) {
        ASTORE_();
        BSTORE_();
        __syncthreads();
        if (k0 + 32 < 288) {
            ALDG_(g_h1, k0 + 32);
            BLDG_(wloc, 288, k0 + 32);
        }
        { int kb2 = 0; KSTEP_(); }
        { int kb2 = 8; KSTEP_(); }
        __syncthreads();
    }

    EPIF_(g_h2, 36, 0, 0, c00); EPIF_(g_h2, 36, 0, 1, c01);
    EPIF_(g_h2, 36, 0, 2, c02); EPIF_(g_h2, 36, 0, 3, c03);
    EPIF_(g_h2, 36, 1, 0, c10); EPIF_(g_h2, 36, 1, 1, c11);
    EPIF_(g_h2, 36, 1, 2, c12); EPIF_(g_h2, 36, 1, 3, c13);
}

// ---------------------------------------------------------------------------
// LL3 on mma.sync. N=128 (n0 via grid.z), K=576, 16 locs.
// ---------------------------------------------------------------------------
__global__ __launch_bounds__(256, 1) void ll3_hmma_k(const float* __restrict__ b3) {
    __shared__ unsigned Ahi[16][128], Alo[16][128];
    __shared__ unsigned Bhi[16][64],  Blo[16][64];
    __shared__ int   rowoffS[576];
    __shared__ float biasS[64];

    int tid  = threadIdx.x;
    int lane = tid & 31;
    int wid  = tid >> 5;
    int wn   = wid & 1;
    int wm   = wid >> 1;
    int loc  = blockIdx.x;
    int m0   = blockIdx.y * 128;
    int n0   = blockIdx.z * 64;
    int li = loc / 4, lj = loc % 4;

    for (int k = tid; k < 576; k += 256) {
        int c = k / 9, r = (k % 9) / 3, cc = k % 3;
        rowoffS[k] = (c * 36 + (li + r) * 6 + (lj + cc)) * BATCH;
    }
    if (tid < 64) biasS[tid] = b3[(n0 + tid) * 16 + loc];
    __syncthreads();

    float4 c00 = {0,0,0,0}, c01 = {0,0,0,0}, c02 = {0,0,0,0}, c03 = {0,0,0,0};
    float4 c10 = {0,0,0,0}, c11 = {0,0,0,0}, c12 = {0,0,0,0}, c13 = {0,0,0,0};

    const unsigned* wloc = g_W3p + (size_t)loc * 128 * 576 + (size_t)n0 * 576;

    float4 va0, va1, vb0, vb1;
    uint4 qa, qb;
    ALDG_(g_h2, 0);
    BLDG_(wloc, 576, 0);

    for (int k0 = 0; k0 < 576; k0 += 32) {
        ASTORE_();
        BSTORE_();
        __syncthreads();
        if (k0 + 32 < 576) {
            ALDG_(g_h2, k0 + 32);
            BLDG_(wloc, 576, k0 + 32);
        }
        { int kb2 = 0; KSTEP_(); }
        { int kb2 = 8; KSTEP_(); }
        __syncthreads();
    }

    EPIF_(g_h3, 16, 0, 0, c00); EPIF_(g_h3, 16, 0, 1, c01);
    EPIF_(g_h3, 16, 0, 2, c02); EPIF_(g_h3, 16, 0, 3, c03);
    EPIF_(g_h3, 16, 1, 0, c10); EPIF_(g_h3, 16, 1, 1, c11);
    EPIF_(g_h3, 16, 1, 2, c12); EPIF_(g_h3, 16, 1, 3, c13);
}

// ---------------------------------------------------------------------------
// Linear head, fp32 h3 in.   [proven]
// ---------------------------------------------------------------------------
__global__ __launch_bounds__(256) void lin_k(const float* __restrict__ Wl,
                                             const float* __restrict__ blin,
                                             float* __restrict__ out) {
    const int CHUNK = 512;
    __shared__ float Wls[CHUNK * 10];
    __shared__ float sacc[8][32][10];

    int m0  = blockIdx.x * 32;
    int tid = threadIdx.x;
    int bl_ = tid % 32;
    int g   = tid / 32;

    float acc[10];
    #pragma unroll
    for (int t = 0; t < 10; t++) acc[t] = 0.f;

    for (int c = 0; c < 4; c++) {
        __syncthreads();
        for (int idx = tid; idx < CHUNK * 10; idx += 256) {
            int fl = idx / 10, t = idx % 10;
            Wls[idx] = Wl[t * 2048 + c * CHUNK + fl];
        }
        __syncthreads();
        int fbase = g * (CHUNK / 8);
        #pragma unroll 4
        for (int fl = fbase; fl < fbase + CHUNK / 8; fl++) {
            int f = c * CHUNK + fl;
            float v = g_h3[f * BATCH + m0 + bl_];
            const float* w = &Wls[fl * 10];
            #pragma unroll
            for (int t = 0; t < 10; t++) acc[t] = fmaf(v, w[t], acc[t]);
        }
    }
    #pragma unroll
    for (int t = 0; t < 10; t++) sacc[g][bl_][t] = acc[t];
    __syncthreads();
    for (int t2 = tid; t2 < 320; t2 += 256) {
        int bb = t2 / 10, t = t2 % 10;
        float s = blin[t];
        #pragma unroll
        for (int gg = 0; gg < 8; gg++) s += sacc[gg][bb][t];
        out[(m0 + bb) * 10 + t] = fmaxf(s, 0.f);
    }
}

// ---------------------------------------------------------------------------
extern "C" void kernel_launch(void* const* d_in, const int* in_sizes, int n_in,
                              void* d_out, int out_size) {
    const float* x  = (const float*)d_in[0];
    const float* W1 = (const float*)d_in[1];
    const float* b1 = (const float*)d_in[2];
    const float* W2 = (const float*)d_in[3];
    const float* b2 = (const float*)d_in[4];
    const float* W3 = (const float*)d_in[5];
    const float* b3 = (const float*)d_in[6];
    const float* Wl = (const float*)d_in[7];
    const float* bl = (const float*)d_in[8];
    float* out = (float*)d_out;

    transpose_x_k<<<dim3(25, 256), dim3(32, 8)>>>(x);
    wpack2_k<<<(36 * 64 * 288 + 255) / 256, 256>>>(W2);
    wpack3_k<<<(16 * 128 * 576 + 255) / 256, 256>>>(W3);
    ll1_k<<<dim3(169, 32), 256>>>(W1, b1);
    ll2_hmma_k<<<dim3(36, 64), 256>>>(b2);
    ll3_hmma_k<<<dim3(16, 64, 2), 256>>>(b3);
    lin_k<<<256, 256>>>(Wl, bl, out);
}

// round 15
// speedup vs baseline: 1.1596x; 1.1596x over previous
#include <cuda_runtime.h>
#include <cuda_bf16.h>
#include <cstdint>

// ---------------------------------------------------------------------------
// FreeConvNetwork, B=8192. LL2 + LL3 on mma.sync bf16 hi/lo-split tensor
// cores (fp32 accumulate). Proven-clean patterns only:
//   - pack/split ONLY in fills (registers) and standalone prep kernels
//   - hmma epilogues write fp32 ONLY (packed epilogues -> 384MiB lmem pool)
//   - conflict-free fragment-plane smem with XOR swizzle col ^= (k2&3)*8
//   - R13 loop structure (R14's register prefetch dropped occupancy 2->1
//     CTAs/SM and regressed; reverted)
// NEW in this round: LL3 CTA reshaped 128m x 64n -> 64m x 128n (no grid.z
// n-split). Halves LL3's A (h2) HBM traffic; B reads double but W3p is
// 4.7MB L2-resident. Warp tile stays 32x32 -> same registers, 2 CTAs/SM.
// value = hi + lo (bf16 each); D = Ahi*Bhi + Ahi*Blo + Alo*Bhi.
// ---------------------------------------------------------------------------

#define BATCH 8192

__device__ float    g_xT [784        * BATCH];   // (28*28, B)
__device__ float    g_h1 [32  * 169  * BATCH];   // fp32
__device__ float    g_h2 [64  * 36   * BATCH];   // fp32
__device__ float    g_h3 [2048       * BATCH];   // fp32
__device__ unsigned g_W2p[36 * 64  * 288];       // (loc, o, k) packed pairs
__device__ unsigned g_W3p[16 * 128 * 576];       // (loc, o, k) packed pairs

__device__ __forceinline__ unsigned pack_pair(float v) {
    __nv_bfloat16 h = __float2bfloat16(v);
    float r = v - __bfloat162float(h);
    __nv_bfloat16 l = __float2bfloat16(r);
    return ((unsigned)__bfloat16_as_ushort(l) << 16) | (unsigned)__bfloat16_as_ushort(h);
}

// Split two fp32 (consecutive k) into hi-fragment and lo-fragment u32s.
__device__ __forceinline__ void pack2(float a, float b, unsigned& hi, unsigned& lo) {
    __nv_bfloat16 ha = __float2bfloat16(a);
    __nv_bfloat16 hb = __float2bfloat16(b);
    float ra = a - __bfloat162float(ha);
    float rb = b - __bfloat162float(hb);
    __nv_bfloat16 la = __float2bfloat16(ra);
    __nv_bfloat16 lb = __float2bfloat16(rb);
    hi = ((unsigned)__bfloat16_as_ushort(hb) << 16) | (unsigned)__bfloat16_as_ushort(ha);
    lo = ((unsigned)__bfloat16_as_ushort(lb) << 16) | (unsigned)__bfloat16_as_ushort(la);
}

#define MMA(c, a0, a1, a2, a3, b) \
    asm volatile( \
        "mma.sync.aligned.m16n8k16.row.col.f32.bf16.bf16.f32 " \
        "{%0,%1,%2,%3}, {%4,%5,%6,%7}, {%8,%9}, {%0,%1,%2,%3};" \
        : "+f"(c.x), "+f"(c.y), "+f"(c.z), "+f"(c.w) \
        : "r"(a0), "r"(a1), "r"(a2), "r"(a3), "r"(b.x), "r"(b.y))

#define PERM_HI(x, y) __byte_perm(x, y, 0x5410)
#define PERM_LO(x, y) __byte_perm(x, y, 0x7632)

// ---------------------------------------------------------------------------
// x (B,784) -> xT (784,B)   [proven]
// ---------------------------------------------------------------------------
__global__ void transpose_x_k(const float* __restrict__ x) {
    __shared__ float tile[32][33];
    int c  = blockIdx.x * 32 + threadIdx.x;
    int r0 = blockIdx.y * 32;
    #pragma unroll
    for (int i = threadIdx.y; i < 32; i += 8) {
        int r = r0 + i;
        tile[i][threadIdx.x] = (c < 784) ? x[r * 784 + c] : 0.f;
    }
    __syncthreads();
    int oc  = r0 + threadIdx.x;
    int or0 = blockIdx.x * 32;
    #pragma unroll
    for (int i = threadIdx.y; i < 32; i += 8) {
        int orow = or0 + i;
        if (orow < 784) g_xT[orow * BATCH + oc] = tile[threadIdx.x][i];
    }
}

// ---------------------------------------------------------------------------
// Weight prep   [proven]
// ---------------------------------------------------------------------------
__global__ void wpack2_k(const float* __restrict__ W) {
    int idx = blockIdx.x * 256 + threadIdx.x;
    if (idx >= 36 * 64 * 288) return;
    int k   = idx % 288;
    int o   = (idx / 288) % 64;
    int loc = idx / (288 * 64);
    g_W2p[idx] = pack_pair(W[(o * 288 + k) * 36 + loc]);
}
__global__ void wpack3_k(const float* __restrict__ W) {
    int idx = blockIdx.x * 256 + threadIdx.x;
    if (idx >= 16 * 128 * 576) return;
    int k   = idx % 576;
    int o   = (idx / 576) % 128;
    int loc = idx / (576 * 128);
    g_W3p[idx] = pack_pair(W[(o * 576 + k) * 16 + loc]);
}

// ---------------------------------------------------------------------------
// LL1 (CUDA core, K=9), fp32 out.   [proven]
// ---------------------------------------------------------------------------
__global__ __launch_bounds__(256) void ll1_k(const float* __restrict__ W1,
                                             const float* __restrict__ b1) {
    int loc = blockIdx.x;
    int i = loc / 13, j = loc % 13;
    int b = blockIdx.y * 256 + threadIdx.x;

    __shared__ float ws[32 * 9];
    __shared__ float bs[32];
    for (int t = threadIdx.x; t < 32 * 9; t += 256) {
        int o = t / 9, k = t % 9;
        ws[t] = W1[(o * 9 + k) * 169 + loc];
    }
    if (threadIdx.x < 32) bs[threadIdx.x] = b1[threadIdx.x * 169 + loc];
    __syncthreads();

    float v[9];
    #pragma unroll
    for (int k = 0; k < 9; k++) {
        int di = k / 3, dj = k % 3;
        v[k] = g_xT[((2 * i + di) * 28 + (2 * j + dj)) * BATCH + b];
    }
    #pragma unroll
    for (int o = 0; o < 32; o++) {
        float acc = bs[o];
        #pragma unroll
        for (int k = 0; k < 9; k++) acc = fmaf(ws[o * 9 + k], v[k], acc);
        g_h1[(o * 169 + loc) * BATCH + b] = fmaxf(acc, 0.f);
    }
}

// ---------------------------------------------------------------------------
// Shared hmma fragment macros (fragment planes + XOR swizzle)  [proven R13]
// ---------------------------------------------------------------------------
#define LOADB2_(NIv, bh, bl) do { \
    int _n  = wn * 32 + (NIv) * 8 + (lane >> 2); \
    int _k2 = kb2 + (lane & 3); \
    int _s  = (_k2 & 3) * 8; \
    bh.x = Bhi[_k2][_n ^ _s];  bh.y = Bhi[_k2 + 4][_n ^ _s]; \
    bl.x = Blo[_k2][_n ^ _s];  bl.y = Blo[_k2 + 4][_n ^ _s]; \
} while (0)

#define MIBLOCK2_(MI, c0, c1, c2, c3) do { \
    int _m  = wm * 32 + (MI) * 16 + (lane >> 2); \
    int _k2 = kb2 + (lane & 3); \
    int _s  = (_k2 & 3) * 8; \
    unsigned ah0 = Ahi[_k2][_m ^ _s],     ah1 = Ahi[_k2][(_m + 8) ^ _s]; \
    unsigned ah2 = Ahi[_k2 + 4][_m ^ _s], ah3 = Ahi[_k2 + 4][(_m + 8) ^ _s]; \
    unsigned al0 = Alo[_k2][_m ^ _s],     al1 = Alo[_k2][(_m + 8) ^ _s]; \
    unsigned al2 = Alo[_k2 + 4][_m ^ _s], al3 = Alo[_k2 + 4][(_m + 8) ^ _s]; \
    MMA(c0, ah0, ah1, ah2, ah3, bh0); \
    MMA(c0, ah0, ah1, ah2, ah3, bl0); \
    MMA(c0, al0, al1, al2, al3, bh0); \
    MMA(c1, ah0, ah1, ah2, ah3, bh1); \
    MMA(c1, ah0, ah1, ah2, ah3, bl1); \
    MMA(c1, al0, al1, al2, al3, bh1); \
    MMA(c2, ah0, ah1, ah2, ah3, bh2); \
    MMA(c2, ah0, ah1, ah2, ah3, bl2); \
    MMA(c2, al0, al1, al2, al3, bh2); \
    MMA(c3, ah0, ah1, ah2, ah3, bh3); \
    MMA(c3, ah0, ah1, ah2, ah3, bl3); \
    MMA(c3, al0, al1, al2, al3, bh3); \
} while (0)

#define KSTEP_() do { \
    uint2 bh0, bl0, bh1, bl1, bh2, bl2, bh3, bl3; \
    LOADB2_(0, bh0, bl0); LOADB2_(1, bh1, bl1); \
    LOADB2_(2, bh2, bl2); LOADB2_(3, bh3, bl3); \
    MIBLOCK2_(0, c00, c01, c02, c03); \
    MIBLOCK2_(1, c10, c11, c12, c13); \
} while (0)

// fp32 epilogue ONLY.   [proven]
#define EPIF_(dst, LOCS, MI, NIv, c) do { \
    int _m = m0 + wm * 32 + (MI) * 16 + (lane >> 2); \
    int _ol = wn * 32 + (NIv) * 8 + (lane & 3) * 2; \
    int _o  = n0 + _ol; \
    float _b0 = biasS[_ol], _b1 = biasS[_ol + 1]; \
    size_t _ba0 = (size_t)(_o * (LOCS) + loc) * BATCH; \
    size_t _ba1 = (size_t)((_o + 1) * (LOCS) + loc) * BATCH; \
    dst[_ba0 + _m]     = fmaxf(c.x + _b0, 0.f); \
    dst[_ba1 + _m]     = fmaxf(c.y + _b1, 0.f); \
    dst[_ba0 + _m + 8] = fmaxf(c.z + _b0, 0.f); \
    dst[_ba1 + _m + 8] = fmaxf(c.w + _b1, 0.f); \
} while (0)

// ---------------------------------------------------------------------------
// LL2 on mma.sync  [R13 verbatim]. N=64, K=288, 36 locs. CTA=(loc, 128m);
// 8 warps 4m x 2n; warp tile 32x32.
// ---------------------------------------------------------------------------
#define AFILL2_(src) do { \
    _Pragma("unroll") \
    for (int p = 0; p < 2; p++) { \
        int k2 = p * 8 + wid; \
        int k  = k0 + k2 * 2; \
        int m4 = lane * 4; \
        float4 v0 = *(const float4*)(src + rowoffS[k]     + m0 + m4); \
        float4 v1 = *(const float4*)(src + rowoffS[k + 1] + m0 + m4); \
        uint4 hv, lv; \
        pack2(v0.x, v1.x, hv.x, lv.x); \
        pack2(v0.y, v1.y, hv.y, lv.y); \
        pack2(v0.z, v1.z, hv.z, lv.z); \
        pack2(v0.w, v1.w, hv.w, lv.w); \
        int sc = m4 ^ ((k2 & 3) * 8); \
        *(uint4*)&Ahi[k2][sc] = hv; \
        *(uint4*)&Alo[k2][sc] = lv; \
    } \
} while (0)

#define BFILL2_(wloc, KREAL) do { \
    _Pragma("unroll") \
    for (int p = 0; p < 2; p++) { \
        int n  = p * 32 + (tid >> 3); \
        int k2 = (tid & 7) * 2; \
        uint4 q = *(const uint4*)(wloc + (size_t)n * (KREAL) + k0 + (tid & 7) * 4); \
        int s0 = (k2 & 3) * 8, s1 = ((k2 + 1) & 3) * 8; \
        Bhi[k2][n ^ s0]     = PERM_HI(q.x, q.y); \
        Blo[k2][n ^ s0]     = PERM_LO(q.x, q.y); \
        Bhi[k2 + 1][n ^ s1] = PERM_HI(q.z, q.w); \
        Blo[k2 + 1][n ^ s1] = PERM_LO(q.z, q.w); \
    } \
} while (0)

__global__ __launch_bounds__(256, 1) void ll2_hmma_k(const float* __restrict__ b2) {
    __shared__ unsigned Ahi[16][128], Alo[16][128];
    __shared__ unsigned Bhi[16][64],  Blo[16][64];
    __shared__ int   rowoffS[288];
    __shared__ float biasS[64];

    int tid  = threadIdx.x;
    int lane = tid & 31;
    int wid  = tid >> 5;
    int wn   = wid & 1;
    int wm   = wid >> 1;
    int loc  = blockIdx.x;
    int m0   = blockIdx.y * 128;
    const int n0 = 0;
    int li = loc / 6, lj = loc % 6;

    for (int k = tid; k < 288; k += 256) {
        int c = k / 9, r = (k % 9) / 3, cc = k % 3;
        rowoffS[k] = (c * 169 + (2 * li + r) * 13 + (2 * lj + cc)) * BATCH;
    }
    if (tid < 64) biasS[tid] = b2[tid * 36 + loc];

    float4 c00 = {0,0,0,0}, c01 = {0,0,0,0}, c02 = {0,0,0,0}, c03 = {0,0,0,0};
    float4 c10 = {0,0,0,0}, c11 = {0,0,0,0}, c12 = {0,0,0,0}, c13 = {0,0,0,0};

    const unsigned* wloc = g_W2p + (size_t)loc * 64 * 288;

    for (int k0 = 0; k0 < 288; k0 += 32) {
        __syncthreads();
        AFILL2_(g_h1);
        BFILL2_(wloc, 288);
        __syncthreads();
        { int kb2 = 0; KSTEP_(); }
        { int kb2 = 8; KSTEP_(); }
    }

    EPIF_(g_h2, 36, 0, 0, c00); EPIF_(g_h2, 36, 0, 1, c01);
    EPIF_(g_h2, 36, 0, 2, c02); EPIF_(g_h2, 36, 0, 3, c03);
    EPIF_(g_h2, 36, 1, 0, c10); EPIF_(g_h2, 36, 1, 1, c11);
    EPIF_(g_h2, 36, 1, 2, c12); EPIF_(g_h2, 36, 1, 3, c13);
}

// ---------------------------------------------------------------------------
// LL3 on mma.sync, reshaped: CTA = (loc, 64m) x FULL 128n. 8 warps 2m x 4n;
// warp tile 32x32 (same registers as R13). A planes [16][64], B [16][128].
// A (h2) traffic halves vs the R13 grid.z=2 split; extra B reads hit L2.
// ---------------------------------------------------------------------------
__global__ __launch_bounds__(256, 1) void ll3_hmma_k(const float* __restrict__ b3) {
    __shared__ unsigned Ahi[16][64],  Alo[16][64];
    __shared__ unsigned Bhi[16][128], Blo[16][128];
    __shared__ int   rowoffS[576];
    __shared__ float biasS[128];

    int tid  = threadIdx.x;
    int lane = tid & 31;
    int wid  = tid >> 5;
    int wn   = wid & 3;                // 4 n-warps x 32 = 128 n
    int wm   = wid >> 2;               // 2 m-warps x 32 = 64 m
    int loc  = blockIdx.x;
    int m0   = blockIdx.y * 64;
    const int n0 = 0;
    int li = loc / 4, lj = loc % 4;

    for (int k = tid; k < 576; k += 256) {
        int c = k / 9, r = (k % 9) / 3, cc = k % 3;
        rowoffS[k] = (c * 36 + (li + r) * 6 + (lj + cc)) * BATCH;
    }
    if (tid < 128) biasS[tid] = b3[tid * 16 + loc];

    float4 c00 = {0,0,0,0}, c01 = {0,0,0,0}, c02 = {0,0,0,0}, c03 = {0,0,0,0};
    float4 c10 = {0,0,0,0}, c11 = {0,0,0,0}, c12 = {0,0,0,0}, c13 = {0,0,0,0};

    const unsigned* wloc = g_W3p + (size_t)loc * 128 * 576;

    for (int k0 = 0; k0 < 576; k0 += 32) {
        __syncthreads();
        // A tile: 64m x 32k. thread -> (k2 = tid>>4, m4 = (tid&15)*4).
        {
            int k2 = tid >> 4;
            int k  = k0 + k2 * 2;
            int m4 = (tid & 15) * 4;
            float4 v0 = *(const float4*)(g_h2 + rowoffS[k]     + m0 + m4);
            float4 v1 = *(const float4*)(g_h2 + rowoffS[k + 1] + m0 + m4);
            uint4 hv, lv;
            pack2(v0.x, v1.x, hv.x, lv.x);
            pack2(v0.y, v1.y, hv.y, lv.y);
            pack2(v0.z, v1.z, hv.z, lv.z);
            pack2(v0.w, v1.w, hv.w, lv.w);
            int sc = m4 ^ ((k2 & 3) * 8);
            *(uint4*)&Ahi[k2][sc] = hv;
            *(uint4*)&Alo[k2][sc] = lv;
        }
        // B tile: 128n x 32k. 4 passes of (n = p*32 + tid>>3, k2 = (tid&7)*2).
        #pragma unroll
        for (int p = 0; p < 4; p++) {
            int n  = p * 32 + (tid >> 3);
            int k2 = (tid & 7) * 2;
            uint4 q = *(const uint4*)(wloc + (size_t)n * 576 + k0 + (tid & 7) * 4);
            int s0 = (k2 & 3) * 8, s1 = ((k2 + 1) & 3) * 8;
            Bhi[k2][n ^ s0]     = PERM_HI(q.x, q.y);
            Blo[k2][n ^ s0]     = PERM_LO(q.x, q.y);
            Bhi[k2 + 1][n ^ s1] = PERM_HI(q.z, q.w);
            Blo[k2 + 1][n ^ s1] = PERM_LO(q.z, q.w);
        }
        __syncthreads();
        { int kb2 = 0; KSTEP_(); }
        { int kb2 = 8; KSTEP_(); }
    }

    EPIF_(g_h3, 16, 0, 0, c00); EPIF_(g_h3, 16, 0, 1, c01);
    EPIF_(g_h3, 16, 0, 2, c02); EPIF_(g_h3, 16, 0, 3, c03);
    EPIF_(g_h3, 16, 1, 0, c10); EPIF_(g_h3, 16, 1, 1, c11);
    EPIF_(g_h3, 16, 1, 2, c12); EPIF_(g_h3, 16, 1, 3, c13);
}

// ---------------------------------------------------------------------------
// Linear head, fp32 h3 in.   [proven]
// ---------------------------------------------------------------------------
__global__ __launch_bounds__(256) void lin_k(const float* __restrict__ Wl,
                                             const float* __restrict__ blin,
                                             float* __restrict__ out) {
    const int CHUNK = 512;
    __shared__ float Wls[CHUNK * 10];
    __shared__ float sacc[8][32][10];

    int m0  = blockIdx.x * 32;
    int tid = threadIdx.x;
    int bl_ = tid % 32;
    int g   = tid / 32;

    float acc[10];
    #pragma unroll
    for (int t = 0; t < 10; t++) acc[t] = 0.f;

    for (int c = 0; c < 4; c++) {
        __syncthreads();
        for (int idx = tid; idx < CHUNK * 10; idx += 256) {
            int fl = idx / 10, t = idx % 10;
            Wls[idx] = Wl[t * 2048 + c * CHUNK + fl];
        }
        __syncthreads();
        int fbase = g * (CHUNK / 8);
        #pragma unroll 4
        for (int fl = fbase; fl < fbase + CHUNK / 8; fl++) {
            int f = c * CHUNK + fl;
            float v = g_h3[f * BATCH + m0 + bl_];
            const float* w = &Wls[fl * 10];
            #pragma unroll
            for (int t = 0; t < 10; t++) acc[t] = fmaf(v, w[t], acc[t]);
        }
    }
    #pragma unroll
    for (int t = 0; t < 10; t++) sacc[g][bl_][t] = acc[t];
    __syncthreads();
    for (int t2 = tid; t2 < 320; t2 += 256) {
        int bb = t2 / 10, t = t2 % 10;
        float s = blin[t];
        #pragma unroll
        for (int gg = 0; gg < 8; gg++) s += sacc[gg][bb][t];
        out[(m0 + bb) * 10 + t] = fmaxf(s, 0.f);
    }
}

// ---------------------------------------------------------------------------
extern "C" void kernel_launch(void* const* d_in, const int* in_sizes, int n_in,
                              void* d_out, int out_size) {
    const float* x  = (const float*)d_in[0];
    const float* W1 = (const float*)d_in[1];
    const float* b1 = (const float*)d_in[2];
    const float* W2 = (const float*)d_in[3];
    const float* b2 = (const float*)d_in[4];
    const float* W3 = (const float*)d_in[5];
    const float* b3 = (const float*)d_in[6];
    const float* Wl = (const float*)d_in[7];
    const float* bl = (const float*)d_in[8];
    float* out = (float*)d_out;

    transpose_x_k<<<dim3(25, 256), dim3(32, 8)>>>(x);
    wpack2_k<<<(36 * 64 * 288 + 255) / 256, 256>>>(W2);
    wpack3_k<<<(16 * 128 * 576 + 255) / 256, 256>>>(W3);
    ll1_k<<<dim3(169, 32), 256>>>(W1, b1);
    ll2_hmma_k<<<dim3(36, 64), 256>>>(b2);
    ll3_hmma_k<<<dim3(16, 128), 256>>>(b3);
    lin_k<<<256, 256>>>(Wl, bl, out);
}